// round 3
// baseline (speedup 1.0000x reference)
#include <cuda_runtime.h>

// ============================================================================
// QuantumLayer: 4 qubits, 2 layers, BATCH=524288. Single kernel.
// TWO SAMPLES PER THREAD, packed lane-wise in f32x2 (SASS FFMA2/FMUL2):
// lane.lo = sample 2t, lane.hi = sample 2t+1. Lanes never interact, so there
// is no pack/unpack anywhere in the gate pipeline.
//
// Algebraic reductions (validated in earlier rounds):
//  - Encoding RY⊗4 on |0000> = rank-1 real product state.
//  - Per-layer RZs commute past other-wire RYs -> one 16-entry diagonal.
//  - Layer-1 diagonal followed only by CNOTs then |amp|^2 -> no-op, dropped.
//  - CNOTs = compile-time register renames (zero instructions).
//  - Weight trig computed once per block into smem, pre-packed as f32x2.
// ============================================================================

using u64 = unsigned long long;

__device__ __forceinline__ u64 mul2(u64 a, u64 b) {
    u64 d; asm("mul.rn.f32x2 %0, %1, %2;" : "=l"(d) : "l"(a), "l"(b)); return d;
}
__device__ __forceinline__ u64 fma2(u64 a, u64 b, u64 c) {
    u64 d; asm("fma.rn.f32x2 %0, %1, %2, %3;" : "=l"(d) : "l"(a), "l"(b), "l"(c)); return d;
}
__device__ __forceinline__ u64 add2(u64 a, u64 b) {
    u64 d; asm("add.rn.f32x2 %0, %1, %2;" : "=l"(d) : "l"(a), "l"(b)); return d;
}
__device__ __forceinline__ u64 pk(float lo, float hi) {
    u64 d; asm("mov.b64 %0, {%1, %2};" : "=l"(d) : "f"(lo), "f"(hi)); return d;
}
__device__ __forceinline__ float2 upk(u64 a) {
    float2 r; asm("mov.b64 {%0, %1}, %2;" : "=f"(r.x), "=f"(r.y) : "l"(a)); return r;
}

// Packed butterfly: (A0, A1) <- (c*A0 - s*A1, s*A0 + c*A1).
__device__ __forceinline__ void bf2(u64& A0, u64& A1, u64 cc, u64 ss, u64 nss) {
    u64 t0 = A0, t1 = A1;
    A0 = fma2(t0, cc, mul2(t1, nss));
    A1 = fma2(t0, ss, mul2(t1, cc));
}

__global__ __launch_bounds__(256, 2)
void circuit_kernel(const float* __restrict__ x, const float* __restrict__ w,
                    float* __restrict__ out, int NPAIR) {
    // ---- per-block prep: weight trig, pre-packed (same value both lanes) ----
    __shared__ u64 s_cc[8], s_ss[8], s_nss[8];   // per RY gate (layer*4+q)
    __shared__ u64 s_pr[16], s_pi[16];           // layer-0 combined RZ diagonal

    int t = threadIdx.x;
    if (t < 8) {
        float hy = 0.5f * w[t * 2];
        float s, c; __sincosf(hy, &s, &c);
        s_cc[t]  = pk(c, c);
        s_ss[t]  = pk(s, s);
        s_nss[t] = pk(-s, -s);
    } else if (t < 24) {
        int idx = t - 8;
        float ang = 0.0f;
        #pragma unroll
        for (int q = 0; q < 4; q++) {
            float hz = 0.5f * w[q * 2 + 1];   // layer 0, wire q, z-weight
            ang += ((idx >> (3 - q)) & 1) ? hz : -hz;
        }
        float s, c; __sincosf(ang, &s, &c);
        s_pr[idx] = pk(c, c);
        s_pi[idx] = pk(s, s);
    }
    __syncthreads();

    int tid = blockIdx.x * blockDim.x + t;
    if (tid >= NPAIR) return;

    const float4* x4 = reinterpret_cast<const float4*>(x);
    float4 xA = x4[2 * tid];
    float4 xB = x4[2 * tid + 1];
    float a4[4] = {xA.x, xA.y, xA.z, xA.w};
    float b4[4] = {xB.x, xB.y, xB.z, xB.w};

    // Encoding: half-angle h = tanh(x) * pi/2, per sample (scalar MUFU path),
    // then pack cos/sin across the two samples.
    u64 pce[4], pse[4];
    #pragma unroll
    for (int q = 0; q < 4; q++) {
        float eA  = __expf(2.0f * a4[q]);
        float thA = 1.0f - __fdividef(2.0f, eA + 1.0f);
        float sA, cA; __sincosf(thA * 1.5707963267948966f, &sA, &cA);
        float eB  = __expf(2.0f * b4[q]);
        float thB = 1.0f - __fdividef(2.0f, eB + 1.0f);
        float sB, cB; __sincosf(thB * 1.5707963267948966f, &sB, &cB);
        pce[q] = pk(cA, cB);
        pse[q] = pk(sA, sB);
    }

    // Real product state (packed): R[i] = amp_i for both samples.
    u64 m01[4], m23[4];
    m01[0] = mul2(pce[0], pce[1]); m01[1] = mul2(pce[0], pse[1]);
    m01[2] = mul2(pse[0], pce[1]); m01[3] = mul2(pse[0], pse[1]);
    m23[0] = mul2(pce[2], pce[3]); m23[1] = mul2(pce[2], pse[3]);
    m23[2] = mul2(pse[2], pce[3]); m23[3] = mul2(pse[2], pse[3]);

    u64 R[16];
    #pragma unroll
    for (int i = 0; i < 16; i++) R[i] = mul2(m01[i >> 2], m23[i & 3]);

    // ---- layer 0: RYs on real state (4 gates, 8 butterflies each) ----
    #pragma unroll
    for (int g = 0; g < 4; g++) {
        int M = 8 >> g;
        u64 cc = s_cc[g], ss = s_ss[g], nss = s_nss[g];
        #pragma unroll
        for (int i = 0; i < 16; i++)
            if (!(i & M)) bf2(R[i], R[i | M], cc, ss, nss);
    }

    // Layer-0 RZ diagonal: real state * complex phase.
    u64 Ar[16], Ai[16];
    #pragma unroll
    for (int i = 0; i < 16; i++) {
        Ar[i] = mul2(R[i], s_pr[i]);
        Ai[i] = mul2(R[i], s_pi[i]);
    }

    // CNOT ring: pure register renames.
    #define CNOT(CM, TM)                                                   \
        _Pragma("unroll")                                                  \
        for (int i = 0; i < 16; i++)                                       \
            if ((i & CM) && !(i & TM)) {                                   \
                u64 tr = Ar[i]; Ar[i] = Ar[i | TM]; Ar[i | TM] = tr;       \
                u64 ti = Ai[i]; Ai[i] = Ai[i | TM]; Ai[i | TM] = ti;       \
            }
    CNOT(8, 4) CNOT(4, 2) CNOT(2, 1) CNOT(1, 8)

    // ---- layer 1: complex RYs ----
    #pragma unroll
    for (int g = 0; g < 4; g++) {
        int M = 8 >> g;
        u64 cc = s_cc[4 + g], ss = s_ss[4 + g], nss = s_nss[4 + g];
        #pragma unroll
        for (int i = 0; i < 16; i++)
            if (!(i & M)) {
                bf2(Ar[i], Ar[i | M], cc, ss, nss);
                bf2(Ai[i], Ai[i | M], cc, ss, nss);
            }
    }

    // Layer-1 RZ diagonal: no effect on |amp|^2 after permutation -> skipped.

    CNOT(8, 4) CNOT(4, 2) CNOT(2, 1) CNOT(1, 8)
    #undef CNOT

    // ---- measurement: p_i = re^2 + im^2, then <Z_q> tree (all packed) ----
    u64 p[16];
    #pragma unroll
    for (int i = 0; i < 16; i++) p[i] = fma2(Ar[i], Ar[i], mul2(Ai[i], Ai[i]));

    const u64 NEG1 = 0xBF800000BF800000ull;   // {-1.0f, -1.0f}

    u64 s2[8], s4[4], s8[2];
    u64 z3 = 0, z2 = 0, z1 = 0;
    #pragma unroll
    for (int j = 0; j < 8; j++) {
        s2[j] = add2(p[2*j], p[2*j+1]);
        u64 d = fma2(p[2*j+1], NEG1, p[2*j]);
        z3 = (j == 0) ? d : add2(z3, d);
    }
    #pragma unroll
    for (int j = 0; j < 4; j++) {
        s4[j] = add2(s2[2*j], s2[2*j+1]);
        u64 d = fma2(s2[2*j+1], NEG1, s2[2*j]);
        z2 = (j == 0) ? d : add2(z2, d);
    }
    #pragma unroll
    for (int j = 0; j < 2; j++) {
        s8[j] = add2(s4[2*j], s4[2*j+1]);
        u64 d = fma2(s4[2*j+1], NEG1, s4[2*j]);
        z1 = (j == 0) ? d : add2(z1, d);
    }
    u64 z0 = fma2(s8[1], NEG1, s8[0]);

    float2 f0 = upk(z0), f1 = upk(z1), f2 = upk(z2), f3 = upk(z3);
    float4* o4 = reinterpret_cast<float4*>(out);
    float4 oA; oA.x = f0.x; oA.y = f1.x; oA.z = f2.x; oA.w = f3.x;
    float4 oB; oB.x = f0.y; oB.y = f1.y; oB.z = f2.y; oB.w = f3.y;
    o4[2 * tid]     = oA;
    o4[2 * tid + 1] = oB;
}

extern "C" void kernel_launch(void* const* d_in, const int* in_sizes, int n_in,
                              void* d_out, int out_size) {
    const float* x = (const float*)d_in[0];     // [B, 4]
    const float* w = (const float*)d_in[1];     // [2, 4, 2]
    float* out = (float*)d_out;                 // [B, 4]
    int B = in_sizes[0] / 4;
    int npair = B / 2;                           // B = 524288, even

    int threads = 256;
    int blocks = (npair + threads - 1) / threads;
    circuit_kernel<<<blocks, threads>>>(x, w, out, npair);
}

// round 4
// speedup vs baseline: 1.1622x; 1.1622x over previous
#include <cuda_runtime.h>

// ============================================================================
// QuantumLayer: 4 qubits, 2 layers, BATCH=524288. One scalar kernel.
//
// Exact algebraic reductions:
//  - Encoding RY(tanh(x)*pi) on |0> followed by layer-0 weight RY on the same
//    wire = single RY with summed angle -> layer-0 RYs cost 4 scalar adds.
//  - State after combined RYs is a REAL rank-1 product state r[16] (24 muls).
//  - Layer-0 RZs commute past other-wire RYs -> one 16-entry complex diagonal
//    (precomputed per block). Layer-1 diagonal precedes only CNOTs + |.|^2,
//    so it is a provable no-op -> dropped.
//  - CNOTs are compile-time register renames (zero instructions).
//  - Everything after the diagonal is a REAL linear map applied independently
//    to Re and Im -> process the two branches sequentially to halve live regs.
// ============================================================================

template <int CM, int TM>
__device__ __forceinline__ void cnot1(float* a) {
    #pragma unroll
    for (int i = 0; i < 16; i++)
        if ((i & CM) && !(i & TM)) {
            float t = a[i]; a[i] = a[i | TM]; a[i | TM] = t;
        }
}

__device__ __forceinline__ void ring(float* a) {
    cnot1<8, 4>(a); cnot1<4, 2>(a); cnot1<2, 1>(a); cnot1<1, 8>(a);
}

// perm -> layer-1 RY gates -> perm, on one real 16-vector.
__device__ __forceinline__ void branch(float* v, const float* c1, const float* s1) {
    ring(v);
    #pragma unroll
    for (int g = 0; g < 4; g++) {
        int M = 8 >> g;
        float c = c1[g], s = s1[g];
        #pragma unroll
        for (int i = 0; i < 16; i++)
            if (!(i & M)) {
                float a0 = v[i], a1 = v[i | M];
                v[i]     = c * a0 - s * a1;
                v[i | M] = s * a0 + c * a1;
            }
    }
    ring(v);
}

__global__ __launch_bounds__(256)
void circuit_kernel(const float* __restrict__ x, const float* __restrict__ w,
                    float* __restrict__ out, int B) {
    // ---- per-block prep ----
    // s_ph[i]  = (cos, sin) of layer-0 combined RZ angle for basis i
    // s_c1/s_s1[q] = cos/sin of layer-1 RY half-angle on wire q
    // s_w0[q]  = layer-0 RY half-angle (folded into encoding)
    __shared__ float2 s_ph[16];
    __shared__ float  s_c1[4], s_s1[4], s_w0[4];

    int t = threadIdx.x;
    if (t < 16) {
        float ang = 0.0f;
        #pragma unroll
        for (int q = 0; q < 4; q++) {
            float hz = 0.5f * w[q * 2 + 1];           // layer 0, wire q, z
            ang += ((t >> (3 - q)) & 1) ? hz : -hz;
        }
        float s, c; __sincosf(ang, &s, &c);
        s_ph[t] = make_float2(c, s);
    } else if (t < 20) {
        int q = t - 16;
        float hy = 0.5f * w[(4 + q) * 2];             // layer 1, wire q, y
        float s, c; __sincosf(hy, &s, &c);
        s_c1[q] = c; s_s1[q] = s;
    } else if (t < 24) {
        int q = t - 20;
        s_w0[q] = 0.5f * w[q * 2];                    // layer 0, wire q, y
    }
    __syncthreads();

    int b = blockIdx.x * blockDim.x + t;
    if (b >= B) return;

    float4 xv = reinterpret_cast<const float4*>(x)[b];
    float xa[4] = {xv.x, xv.y, xv.z, xv.w};

    // Combined half-angle: tanh(x)*pi/2 + 0.5*w_y0  (layer-0 RY folded in).
    float ce[4], se[4];
    #pragma unroll
    for (int q = 0; q < 4; q++) {
        float e  = __expf(2.0f * xa[q]);
        float th = 1.0f - __fdividef(2.0f, e + 1.0f);       // tanh(x)
        float h  = fmaf(th, 1.5707963267948966f, s_w0[q]);
        __sincosf(h, &se[q], &ce[q]);
    }

    // Real rank-1 product state.
    float m01[4], m23[4];
    m01[0] = ce[0] * ce[1]; m01[1] = ce[0] * se[1];
    m01[2] = se[0] * ce[1]; m01[3] = se[0] * se[1];
    m23[0] = ce[2] * ce[3]; m23[1] = ce[2] * se[3];
    m23[2] = se[2] * ce[3]; m23[3] = se[2] * se[3];

    float r[16];
    #pragma unroll
    for (int i = 0; i < 16; i++) r[i] = m01[i >> 2] * m23[i & 3];

    // Hoist layer-1 gate constants.
    float c1[4], s1[4];
    #pragma unroll
    for (int q = 0; q < 4; q++) { c1[q] = s_c1[q]; s1[q] = s_s1[q]; }

    // ---- Re branch ----
    float v[16];
    #pragma unroll
    for (int i = 0; i < 16; i++) v[i] = r[i] * s_ph[i].x;
    branch(v, c1, s1);
    float p[16];
    #pragma unroll
    for (int i = 0; i < 16; i++) p[i] = v[i] * v[i];

    // ---- Im branch (r consumed) ----
    #pragma unroll
    for (int i = 0; i < 16; i++) v[i] = r[i] * s_ph[i].y;
    branch(v, c1, s1);
    #pragma unroll
    for (int i = 0; i < 16; i++) p[i] = fmaf(v[i], v[i], p[i]);

    // ---- <Z_q> tree ----
    float s2[8], s4[4], s8[2];
    float z3 = 0.0f, z2 = 0.0f, z1 = 0.0f;
    #pragma unroll
    for (int j = 0; j < 8; j++) { s2[j] = p[2*j] + p[2*j+1]; z3 += p[2*j] - p[2*j+1]; }
    #pragma unroll
    for (int j = 0; j < 4; j++) { s4[j] = s2[2*j] + s2[2*j+1]; z2 += s2[2*j] - s2[2*j+1]; }
    #pragma unroll
    for (int j = 0; j < 2; j++) { s8[j] = s4[2*j] + s4[2*j+1]; z1 += s4[2*j] - s4[2*j+1]; }
    float z0 = s8[0] - s8[1];

    float4 o; o.x = z0; o.y = z1; o.z = z2; o.w = z3;
    reinterpret_cast<float4*>(out)[b] = o;
}

extern "C" void kernel_launch(void* const* d_in, const int* in_sizes, int n_in,
                              void* d_out, int out_size) {
    const float* x = (const float*)d_in[0];     // [B, 4]
    const float* w = (const float*)d_in[1];     // [2, 4, 2]
    float* out = (float*)d_out;                 // [B, 4]
    int B = in_sizes[0] / 4;

    int threads = 256;
    int blocks = (B + threads - 1) / threads;
    circuit_kernel<<<blocks, threads>>>(x, w, out, B);
}

// round 5
// speedup vs baseline: 1.5248x; 1.3120x over previous
#include <cuda_runtime.h>

// ============================================================================
// QuantumLayer (4 qubits, 2 layers, BATCH=524288) in the HEISENBERG PICTURE.
//
// State before the first CNOT ring is a product state per wire:
//   |psi_q> = RZ(phi_q) RY(a_q) |0>,  a_q = pi*tanh(x_q) + w[0][q][0] (RYs on
//   the same wire add),  phi_q = w[0][q][1].  Bloch vector:
//   x_q = sin a cos phi,  y_q = sin a sin phi,  z_q = cos a.
// The layer-1 RZ diagonal commutes to the measurement and drops (|.|^2).
// Conjugating Z_q back through ring2, RY-layer (Z -> cos t Z - sin t X),
// and ring1 yields 36 Pauli-string terms total; each expectation is a
// product of per-wire Bloch components times a weight-only coefficient.
//
// Coefficient k for term with wire-set W and s-selection S:
//   coef = sign * prod_{j in W} (j in S ? sin theta_j : cos theta_j),
//   theta_j = w[1][j][0].  Encoded in c_tbl: bits0-3 = S, bits4-7 = W,
//   bit8 = negative sign.
// ============================================================================

__constant__ unsigned short c_tbl[36] = {
    // q0 (wires {1,2,3}):  Z-pattern order ZZZ,ZZX,ZXZ,ZXX,XZZ,XZX,XXZ,XXX
    0x0E0, 0x1E8, 0x0E4, 0x1EC, 0x1E2, 0x1EA, 0x1E6, 0x1EE,
    // q1 (wires {0,1})
    0x030, 0x032, 0x031, 0x033,
    // q2 (wires {0,1,2})
    0x070, 0x074, 0x172, 0x176, 0x171, 0x175, 0x173, 0x177,
    // q3 (wires {0,1,2,3})
    0x0F0, 0x0F8, 0x1F4, 0x1FC, 0x0F2, 0x1FA, 0x0F6, 0x1FE,
    0x0F1, 0x0F9, 0x1F5, 0x1FD, 0x0F3, 0x0FB, 0x0F7, 0x0FF
};

__global__ __launch_bounds__(256)
void circuit_kernel(const float* __restrict__ x, const float* __restrict__ w,
                    float* __restrict__ out, int B) {
    __shared__ float s_cph[4], s_sph[4], s_pipw[4];   // cos/sin(phi), pi + w0y
    __shared__ float s_cth[4], s_sth[4];              // cos/sin(theta layer 1)
    __shared__ float s_coef[36];

    const int t = threadIdx.x;
    if (t < 4) {
        float sp, cp; __sincosf(w[2 * t + 1], &sp, &cp);
        s_sph[t] = sp; s_cph[t] = cp;
        s_pipw[t] = 3.14159265358979f + w[2 * t];
    } else if (t < 8) {
        int j = t - 4;
        float st, ct; __sincosf(w[8 + 2 * j], &st, &ct);
        s_sth[j] = st; s_cth[j] = ct;
    }
    __syncthreads();
    if (t < 36) {
        unsigned e = c_tbl[t];
        float v = 1.0f;
        #pragma unroll
        for (int j = 0; j < 4; j++)
            if ((e >> (4 + j)) & 1) v *= ((e >> j) & 1) ? s_sth[j] : s_cth[j];
        s_coef[t] = (e & 0x100) ? -v : v;
    }
    __syncthreads();

    int b = blockIdx.x * blockDim.x + t;
    if (b >= B) return;

    float4 xv = reinterpret_cast<const float4*>(x)[b];
    float xs[4] = {xv.x, xv.y, xv.z, xv.w};

    // Per-wire Bloch vectors.
    float X[4], Y[4], Z[4];
    #pragma unroll
    for (int q = 0; q < 4; q++) {
        float e  = __expf(2.0f * xs[q]);
        // a = pi*tanh(x) + w0y = (pi + w0y) - 2pi/(e^{2x}+1)
        float a  = s_pipw[q] - __fdividef(6.283185307179586f, e + 1.0f);
        float sa, ca; __sincosf(a, &sa, &ca);
        X[q] = sa * s_cph[q];
        Y[q] = sa * s_sph[q];
        Z[q] = ca;
    }

    // Shared sub-products.
    float x01 = X[0]*X[1], y01 = Y[0]*Y[1], y12 = Y[1]*Y[2], y23 = Y[2]*Y[3];
    float x12 = X[1]*X[2], x23 = X[2]*X[3], z13 = Z[1]*Z[3], zx23 = Z[2]*X[3];
    float z12 = Z[1]*Z[2], x02 = X[0]*X[2], z23 = Z[2]*Z[3], yz01 = Y[0]*Z[1];

    const float* C = s_coef;
    float a0, a1, a2, a3;

    // <Z_0>
    a0  = C[0] * (Z[0] * z13);                       // z0 z1 z3
    a0 = fmaf(C[1], x01 * zx23, a0);                 // x0 x1 z2 x3
    a0 = fmaf(C[2], y23, a0);                        // y2 y3
    a0 = fmaf(C[3], y01 * X[2], a0);                 // y0 y1 x2
    a0 = fmaf(C[4], x12 * Z[3], a0);                 // x1 x2 z3
    a0 = fmaf(C[5], (yz01 * Y[2]) * X[3], a0);       // y0 z1 y2 x3
    a0 = fmaf(C[6], ((Z[0] * Y[1]) * Z[2]) * Y[3], a0); // z0 y1 z2 y3
    a0 = fmaf(C[7], X[0], a0);                       // x0

    // <Z_1>
    a1  = C[8] * (Z[0] * z23);                       // z0 z2 z3
    a1 = fmaf(C[9],  y12 * Z[3], a1);                // y1 y2 z3
    a1 = fmaf(C[10], y01, a1);                       // y0 y1
    a1 = fmaf(C[11], x02, a1);                       // x0 x2

    // <Z_2>
    a2  = C[12] * z13;                               // z1 z3
    a2 = fmaf(C[13], Z[0] * y23, a2);                // z0 y2 y3
    a2 = fmaf(C[14], (Z[0] * x12) * Z[3], a2);       // z0 x1 x2 z3
    a2 = fmaf(C[15], (Y[1] * Z[2]) * Y[3], a2);      // y1 z2 y3
    a2 = fmaf(C[16], x01 * Z[2], a2);                // x0 x1 z2
    a2 = fmaf(C[17], y01 * x23, a2);                 // y0 y1 x2 x3
    a2 = fmaf(C[18], yz01 * Y[2], a2);               // y0 z1 y2
    a2 = fmaf(C[19], X[0] * X[3], a2);               // x0 x3

    // <Z_3>
    a3  = C[20] * (Z[0] * Z[2]);                     // z0 z2
    a3 = fmaf(C[21], X[0] * (Y[1] * Y[3]), a3);      // x0 y1 y3
    a3 = fmaf(C[22], Z[1] * x23, a3);                // z1 x2 x3
    a3 = fmaf(C[23], ((Y[0] * X[1]) * Y[2]) * Z[3], a3); // y0 x1 y2 z3
    a3 = fmaf(C[24], y12, a3);                       // y1 y2
    a3 = fmaf(C[25], (Y[0] * X[2]) * Y[3], a3);      // y0 x2 y3
    a3 = fmaf(C[26], Z[0] * (X[1] * X[3]), a3);      // z0 x1 x3
    a3 = fmaf(C[27], (X[0] * z12) * Z[3], a3);       // x0 z1 z2 z3
    a3 = fmaf(C[28], y01 * Z[3], a3);                // y0 y1 z3
    a3 = fmaf(C[29], zx23, a3);                      // z2 x3
    a3 = fmaf(C[30], x01 * y23, a3);                 // x0 x1 y2 y3
    a3 = fmaf(C[31], (Z[0] * Z[1]) * X[2], a3);      // z0 z1 x2
    a3 = fmaf(C[32], x02 * Z[3], a3);                // x0 x2 z3
    a3 = fmaf(C[33], (Z[0] * y12) * X[3], a3);       // z0 y1 y2 x3
    a3 = fmaf(C[34], (yz01 * Z[2]) * Y[3], a3);      // y0 z1 z2 y3
    a3 = fmaf(C[35], X[1], a3);                      // x1

    float4 o; o.x = a0; o.y = a1; o.z = a2; o.w = a3;
    reinterpret_cast<float4*>(out)[b] = o;
}

extern "C" void kernel_launch(void* const* d_in, const int* in_sizes, int n_in,
                              void* d_out, int out_size) {
    const float* x = (const float*)d_in[0];     // [B, 4]
    const float* w = (const float*)d_in[1];     // [2, 4, 2]
    float* out = (float*)d_out;                 // [B, 4]
    int B = in_sizes[0] / 4;

    int threads = 256;
    int blocks = (B + threads - 1) / threads;
    circuit_kernel<<<blocks, threads>>>(x, w, out, B);
}